// round 1
// baseline (speedup 1.0000x reference)
#include <cuda_runtime.h>

// Fused HybridSamplerConv:
//   logit = <data[b], conv_w> + conv_b ; conv = sigmoid(logit)
//   h = tanh([in0,in1,conv] @ w1 + b1) ; out = softmax(h @ w2 + b2)
// Pure streaming kernel: 24 B in + 8 B out per sample. 2 samples/thread,
// all 128-bit loads/stores.

__device__ __forceinline__ float tanh_fast(float x) {
    float y;
    asm("tanh.approx.f32 %0, %1;" : "=f"(y) : "f"(x));
    return y;
}

__device__ __forceinline__ float sigmoid_fast(float x) {
    // 1 / (1 + exp(-x))
    return 1.0f / (1.0f + __expf(-x));
}

struct Params {
    float cw0, cw1, cw2, cw3, cb;
    float w1[12];   // [3,4] row-major
    float b1[4];
    float w2[8];    // [4,2] row-major
    float b2[2];
};

__global__ void __launch_bounds__(256)
hybrid_sampler_kernel(const float4* __restrict__ inp,   // [B/2] packs 2 samples' (in0,in1)
                      const float4* __restrict__ data,  // [B]   one float4 per sample
                      const float*  __restrict__ conv_w,
                      const float*  __restrict__ conv_b,
                      const float*  __restrict__ w1,
                      const float*  __restrict__ b1,
                      const float*  __restrict__ w2,
                      const float*  __restrict__ b2,
                      float4*       __restrict__ out,   // [B/2] packs 2 samples' (o0,o1)
                      int npairs)
{
    int i = blockIdx.x * blockDim.x + threadIdx.x;
    if (i >= npairs) return;

    // --- uniform parameter loads (L1 broadcast) ---
    Params p;
    p.cw0 = __ldg(conv_w + 0); p.cw1 = __ldg(conv_w + 1);
    p.cw2 = __ldg(conv_w + 2); p.cw3 = __ldg(conv_w + 3);
    p.cb  = __ldg(conv_b);
#pragma unroll
    for (int j = 0; j < 12; ++j) p.w1[j] = __ldg(w1 + j);
#pragma unroll
    for (int j = 0; j < 4;  ++j) p.b1[j] = __ldg(b1 + j);
#pragma unroll
    for (int j = 0; j < 8;  ++j) p.w2[j] = __ldg(w2 + j);
    p.b2[0] = __ldg(b2 + 0); p.b2[1] = __ldg(b2 + 1);

    // --- streaming loads: 2 samples ---
    float4 in2 = inp[i];          // (in0_a, in1_a, in0_b, in1_b)
    float4 da  = data[2 * i + 0]; // sample a: 2x2 patch
    float4 db  = data[2 * i + 1]; // sample b

    float4 result;

#pragma unroll
    for (int s = 0; s < 2; ++s) {
        float in0 = (s == 0) ? in2.x : in2.z;
        float in1 = (s == 0) ? in2.y : in2.w;
        float4 d  = (s == 0) ? da : db;

        // conv 2x2 as dot product + bias, then sigmoid (THRESHOLD = 0)
        float logit = fmaf(d.x, p.cw0, fmaf(d.y, p.cw1,
                      fmaf(d.z, p.cw2, fmaf(d.w, p.cw3, p.cb))));
        float conv = sigmoid_fast(logit);

        // h = tanh([in0, in1, conv] @ w1 + b1)
        float h[4];
#pragma unroll
        for (int j = 0; j < 4; ++j) {
            float a = fmaf(in0, p.w1[0 * 4 + j],
                      fmaf(in1, p.w1[1 * 4 + j],
                      fmaf(conv, p.w1[2 * 4 + j], p.b1[j])));
            h[j] = tanh_fast(a);
        }

        // z = h @ w2 + b2   (2 logits)
        float z0 = p.b2[0], z1 = p.b2[1];
#pragma unroll
        for (int j = 0; j < 4; ++j) {
            z0 = fmaf(h[j], p.w2[j * 2 + 0], z0);
            z1 = fmaf(h[j], p.w2[j * 2 + 1], z1);
        }

        // softmax over 2: exact & symmetric
        float e = __expf(z1 - z0);
        float r = 1.0f / (1.0f + e);
        float o0 = r;
        float o1 = e * r;

        if (s == 0) { result.x = o0; result.y = o1; }
        else        { result.z = o0; result.w = o1; }
    }

    out[i] = result;
}

extern "C" void kernel_launch(void* const* d_in, const int* in_sizes, int n_in,
                              void* d_out, int out_size)
{
    const float* inp    = (const float*)d_in[0]; // [B,2]
    const float* data   = (const float*)d_in[1]; // [B,2,2]
    const float* conv_w = (const float*)d_in[2]; // [2,2]
    const float* conv_b = (const float*)d_in[3]; // scalar
    const float* w1     = (const float*)d_in[4]; // [3,4]
    const float* b1     = (const float*)d_in[5]; // [4]
    const float* w2     = (const float*)d_in[6]; // [4,2]
    const float* b2     = (const float*)d_in[7]; // [2]
    float* out          = (float*)d_out;         // [B,2]

    int B = in_sizes[0] / 2;       // samples
    int npairs = B / 2;            // 2 samples per thread (B is even)

    int threads = 256;
    int blocks = (npairs + threads - 1) / threads;

    hybrid_sampler_kernel<<<blocks, threads>>>(
        (const float4*)inp, (const float4*)data,
        conv_w, conv_b, w1, b1, w2, b2,
        (float4*)out, npairs);
}